// round 7
// baseline (speedup 1.0000x reference)
#include <cuda_runtime.h>
#include <cuda_bf16.h>
#include <math.h>
#include <stdint.h>

#define NTOK   8192
#define DMODEL 2048
#define DEXP   1024
#define DFFN   1024
#define NE     8
#define TOPK   2
#define CAP    2560
#define NROUTE (NTOK*TOPK)
#define NSLOT  (NE*CAP)

// ---------------- scratch (device globals) ----------------
__device__ float g_topv[NROUTE];
__device__ int   g_topi[NROUTE];
__device__ float g_gate[NTOK];
__device__ float g_imp[NE];
__device__ int   g_cnt[NE];
__device__ int   g_slot[NROUTE];
__device__ int   g_rows[NE];
__device__ int   g_rtok[NSLOT];

// bf16 split operands
__device__ __nv_bfloat16 g_Xhi[NTOK*DMODEL],  g_Xlo[NTOK*DMODEL];
__device__ __nv_bfloat16 g_W1hi[NE*DEXP*DMODEL], g_W1lo[NE*DEXP*DMODEL];   // [e][N=DEXP][K=DMODEL]
__device__ __nv_bfloat16 g_W2hi[NE*DMODEL*DEXP], g_W2lo[NE*DMODEL*DEXP];   // [e][N=DMODEL][K=DEXP]
__device__ __nv_bfloat16 g_SW1hi[DFFN*DMODEL], g_SW1lo[DFFN*DMODEL];       // [N=DFFN][K=DMODEL]
__device__ __nv_bfloat16 g_SW2hi[DMODEL*DFFN], g_SW2lo[DMODEL*DFFN];       // [N=DMODEL][K=DFFN]
__device__ __nv_bfloat16 g_Hhi[NSLOT*DEXP],   g_Hlo[NSLOT*DEXP];
__device__ __nv_bfloat16 g_HShi[NTOK*DFFN],   g_HSlo[NTOK*DFFN];
__device__ float g_EO[(size_t)NSLOT*DMODEL];

__device__ __forceinline__ float gelu_exact(float v) {
    return 0.5f * v * (1.0f + erff(v * 0.70710678118654752f));
}

// ---------------- PTX helpers (base ISA only: cp.async / ldmatrix / mma.sync) ----
__device__ __forceinline__ uint32_t smem_u32(const void* p) {
    uint32_t a;
    asm("{ .reg .u64 t; cvta.to.shared.u64 t, %1; cvt.u32.u64 %0, t; }" : "=r"(a) : "l"(p));
    return a;
}
__device__ __forceinline__ void cp_async16(uint32_t dst, const void* src) {
    asm volatile("cp.async.cg.shared.global [%0], [%1], 16;\n" :: "r"(dst), "l"(src));
}
__device__ __forceinline__ void cp_commit() { asm volatile("cp.async.commit_group;\n"); }
template<int N> __device__ __forceinline__ void cp_wait() {
    asm volatile("cp.async.wait_group %0;\n" :: "n"(N));
}

#define LDM4(r0, r1, r2, r3, addr) \
    asm volatile("ldmatrix.sync.aligned.m8n8.x4.shared.b16 {%0,%1,%2,%3}, [%4];" \
        : "=r"(r0), "=r"(r1), "=r"(r2), "=r"(r3) : "r"(addr))

#define MMA_BF16(d, a, b) \
    asm volatile("mma.sync.aligned.m16n8k16.row.col.f32.bf16.bf16.f32 " \
        "{%0,%1,%2,%3}, {%4,%5,%6,%7}, {%8,%9}, {%0,%1,%2,%3};" \
        : "+f"((d)[0]), "+f"((d)[1]), "+f"((d)[2]), "+f"((d)[3]) \
        : "r"((a)[0]), "r"((a)[1]), "r"((a)[2]), "r"((a)[3]), \
          "r"((b)[0]), "r"((b)[1]))

// ---------------- init ----------------
__global__ void init_kernel() {
    if (threadIdx.x < NE) { g_imp[threadIdx.x] = 0.0f; g_cnt[threadIdx.x] = 0; }
}

// ---------------- router: one warp per token ----------------
__global__ __launch_bounds__(256) void router_kernel(
    const float* __restrict__ x, const float* __restrict__ rw,
    const float* __restrict__ gw)
{
    __shared__ float s_imp[NE];
    __shared__ int   s_cnt[NE];
    if (threadIdx.x < NE) { s_imp[threadIdx.x] = 0.0f; s_cnt[threadIdx.x] = 0; }
    __syncthreads();

    int warp = (blockIdx.x * blockDim.x + threadIdx.x) >> 5;
    int lane = threadIdx.x & 31;
    if (warp < NTOK) {
        const float4* xv = (const float4*)(x + (size_t)warp * DMODEL);
        float acc[9];
        #pragma unroll
        for (int v = 0; v < 9; v++) acc[v] = 0.0f;
        for (int i = lane; i < DMODEL/4; i += 32) {
            float4 xa = xv[i];
            #pragma unroll
            for (int e = 0; e < NE; e++) {
                float4 w = ((const float4*)(rw + (size_t)e * DMODEL))[i];
                acc[e] += xa.x*w.x + xa.y*w.y + xa.z*w.z + xa.w*w.w;
            }
            float4 g = ((const float4*)gw)[i];
            acc[8] += xa.x*g.x + xa.y*g.y + xa.z*g.z + xa.w*g.w;
        }
        #pragma unroll
        for (int off = 16; off; off >>= 1) {
            #pragma unroll
            for (int v = 0; v < 9; v++)
                acc[v] += __shfl_xor_sync(0xffffffffu, acc[v], off);
        }
        if (lane == 0) {
            float mx = acc[0];
            #pragma unroll
            for (int e = 1; e < NE; e++) mx = fmaxf(mx, acc[e]);
            float p[NE]; float sum = 0.0f;
            #pragma unroll
            for (int e = 0; e < NE; e++) { p[e] = expf(acc[e] - mx); sum += p[e]; }
            float inv = 1.0f / sum;
            #pragma unroll
            for (int e = 0; e < NE; e++) p[e] *= inv;

            int i0 = 0; float v0 = p[0];
            #pragma unroll
            for (int e = 1; e < NE; e++) if (p[e] > v0) { v0 = p[e]; i0 = e; }
            int i1 = -1; float v1 = -1.0f;
            #pragma unroll
            for (int e = 0; e < NE; e++) if (e != i0 && p[e] > v1) { v1 = p[e]; i1 = e; }

            g_topi[warp*2]   = i0; g_topv[warp*2]   = v0;
            g_topi[warp*2+1] = i1; g_topv[warp*2+1] = v1;
            g_gate[warp] = 1.0f / (1.0f + expf(-acc[8]));
            #pragma unroll
            for (int e = 0; e < NE; e++) atomicAdd(&s_imp[e], p[e]);
            atomicAdd(&s_cnt[i0], 1);
            atomicAdd(&s_cnt[i1], 1);
        }
    }
    __syncthreads();
    if (threadIdx.x < NE) {
        atomicAdd(&g_imp[threadIdx.x], s_imp[threadIdx.x]);
        atomicAdd(&g_cnt[threadIdx.x], s_cnt[threadIdx.x]);
    }
}

// ---------------- stable routing scan (single block) ----------------
#define NCHUNK 64
#define CHUNK  (NROUTE/NCHUNK)   // 256
__global__ __launch_bounds__(256) void scan_kernel() {
    __shared__ unsigned char ids[NROUTE];
    __shared__ int hist[NCHUNK][NE];
    __shared__ int base[NCHUNK][NE];
    int tid = threadIdx.x;
    for (int r = tid; r < NROUTE; r += 256) ids[r] = (unsigned char)g_topi[r];
    __syncthreads();
    if (tid < NCHUNK) {
        int h[NE];
        #pragma unroll
        for (int e = 0; e < NE; e++) h[e] = 0;
        for (int j = 0; j < CHUNK; j++) h[ids[tid*CHUNK + j]]++;
        #pragma unroll
        for (int e = 0; e < NE; e++) hist[tid][e] = h[e];
    }
    __syncthreads();
    if (tid == 0) {
        int run[NE];
        #pragma unroll
        for (int e = 0; e < NE; e++) run[e] = 0;
        for (int c = 0; c < NCHUNK; c++) {
            #pragma unroll
            for (int e = 0; e < NE; e++) { base[c][e] = run[e]; run[e] += hist[c][e]; }
        }
        #pragma unroll
        for (int e = 0; e < NE; e++) g_rows[e] = (run[e] < CAP) ? run[e] : CAP;
    }
    __syncthreads();
    if (tid < NCHUNK) {
        int pos[NE];
        #pragma unroll
        for (int e = 0; e < NE; e++) pos[e] = base[tid][e];
        for (int j = 0; j < CHUNK; j++) {
            int r = tid*CHUNK + j;
            int e = ids[r];
            int rank = pos[e]++;
            if (rank < CAP) {
                int s = e*CAP + rank;
                g_slot[r]  = s;
                g_rtok[s]  = r >> 1;
            } else {
                g_slot[r] = -1;
            }
        }
    }
}

// ---------------- split conversion (elementwise, float4) ----------------
__global__ __launch_bounds__(256) void k_split(
    const float* __restrict__ in, __nv_bfloat16* __restrict__ hi,
    __nv_bfloat16* __restrict__ lo, int n4)
{
    int i = blockIdx.x * 256 + threadIdx.x;
    if (i >= n4) return;
    float4 v = ((const float4*)in)[i];
    __nv_bfloat16 h0 = __float2bfloat16(v.x);
    __nv_bfloat16 h1 = __float2bfloat16(v.y);
    __nv_bfloat16 h2 = __float2bfloat16(v.z);
    __nv_bfloat16 h3 = __float2bfloat16(v.w);
    __nv_bfloat162* H = (__nv_bfloat162*)hi;
    __nv_bfloat162* L = (__nv_bfloat162*)lo;
    H[2*i]   = __nv_bfloat162(h0, h1);
    H[2*i+1] = __nv_bfloat162(h2, h3);
    L[2*i]   = __nv_bfloat162(__float2bfloat16(v.x - __bfloat162float(h0)),
                              __float2bfloat16(v.y - __bfloat162float(h1)));
    L[2*i+1] = __nv_bfloat162(__float2bfloat16(v.z - __bfloat162float(h2)),
                              __float2bfloat16(v.w - __bfloat162float(h3)));
}

// ---------------- transpose + split: in [z][R][C] fp32 -> out [z][C][R] bf16 hi/lo --------
__global__ __launch_bounds__(256) void k_tsplit(
    const float* __restrict__ in, __nv_bfloat16* __restrict__ hi,
    __nv_bfloat16* __restrict__ lo, int R, int C)
{
    __shared__ float t[32][33];
    size_t mat = (size_t)blockIdx.z * R * C;
    int c0 = blockIdx.x * 32, r0 = blockIdx.y * 32;
    for (int y = threadIdx.y; y < 32; y += 8)
        t[y][threadIdx.x] = in[mat + (size_t)(r0 + y) * C + c0 + threadIdx.x];
    __syncthreads();
    for (int y = threadIdx.y; y < 32; y += 8) {
        float v = t[threadIdx.x][y];   // element (r0+tx, c0+y)
        __nv_bfloat16 h = __float2bfloat16(v);
        size_t o = mat + (size_t)(c0 + y) * R + r0 + threadIdx.x;
        hi[o] = h;
        lo[o] = __float2bfloat16(v - __bfloat162float(h));
    }
}

// ---------------- HMMA GEMM: CTA 128x256, Kstage 32, 3-stage cp.async, bf16x3 ----
// 256 threads = 8 warps in 2(M) x 4(N) grid, warp tile 64x64.
// LDS reuse: 16 LDM4 per warp-k16 feed 96 MMAs (6 MMA / LDM4).
// MODE 0: routed gemm1  A=gather(Xhi/lo)  B=W1t[e]   K=2048 N=1024 -> gelu -> Hhi/lo
// MODE 1: routed gemm2  A=Hhi/lo[e]       B=W2t[e]   K=1024 N=2048 -> EO (fp32)
// MODE 2: shared gemm1  A=Xhi/lo          B=SW1      K=2048 N=1024 -> gelu -> HShi/lo
// MODE 3: shared gemm2  A=HShi/lo         B=SW2      K=1024 N=2048 -> combine -> out
//
// smem rows: 32 bf16 + 8 pad = 80B, conflict-free ldmatrix.
#define SROWB    80
#define A_TILE_B 10240         // 128*80
#define B_TILE_B 20480         // 256*80
#define STAGE    61440         // Ah + Al + Bh + Bl
#define NSTAGE   3
#define GEMM_SMEM (STAGE*NSTAGE)   // 184320

template<int MODE>
__global__ __launch_bounds__(256)
void gemm_mma(float* __restrict__ outp)
{
    constexpr int KTOT = (MODE == 0 || MODE == 2) ? DMODEL : DEXP;
    constexpr int S = KTOT / 32;

    extern __shared__ char smem[];
    uint32_t sb0 = smem_u32(smem);
    int tid = threadIdx.x, wid = tid >> 5, lane = tid & 31;
    int wm = wid >> 2, wn = wid & 3;     // warp grid 2 (M) x 4 (N)

    int e    = (MODE < 2) ? blockIdx.z : 0;
    int rows = (MODE < 2) ? g_rows[e] : NTOK;
    int row0 = blockIdx.y * 128;
    if (row0 >= rows) return;
    int n0 = blockIdx.x * 256;

    const __nv_bfloat16 *Ah, *Al, *Bh, *Bl;
    if (MODE == 0) { Ah = g_Xhi;  Al = g_Xlo;
                     Bh = g_W1hi + (size_t)e * DEXP * DMODEL;
                     Bl = g_W1lo + (size_t)e * DEXP * DMODEL; }
    if (MODE == 1) { Ah = g_Hhi;  Al = g_Hlo;
                     Bh = g_W2hi + (size_t)e * DMODEL * DEXP;
                     Bl = g_W2lo + (size_t)e * DMODEL * DEXP; }
    if (MODE == 2) { Ah = g_Xhi;  Al = g_Xlo;  Bh = g_SW1hi; Bl = g_SW1lo; }
    if (MODE == 3) { Ah = g_HShi; Al = g_HSlo; Bh = g_SW2hi; Bl = g_SW2lo; }

    // ---- fill addressing ----
    // A: 512 16B-chunks per tensor (128 rows x 4 segs), 2 per thread.
    // B: 1024 chunks per tensor (256 rows x 4 segs), 4 per thread.
    size_t aoff[2]; uint32_t adst[2];
    #pragma unroll
    for (int i = 0; i < 2; i++) {
        int c = tid + 256 * i;
        int rrow = c >> 2, seg = c & 3;
        size_t srow;
        if (MODE == 0) {
            int gr = row0 + rrow;
            int tok = (gr < rows) ? g_rtok[e * CAP + gr] : 0;
            srow = (size_t)tok * DMODEL;
        } else if (MODE == 1) {
            srow = (size_t)(e * CAP + row0 + rrow) * DEXP;
        } else {
            srow = (size_t)(row0 + rrow) * KTOT;
        }
        aoff[i] = srow + seg * 8;
        adst[i] = rrow * SROWB + seg * 16;
    }
    size_t boff[4]; uint32_t bdst[4];
    #pragma unroll
    for (int i = 0; i < 4; i++) {
        int c = tid + 256 * i;
        int rrow = c >> 2, seg = c & 3;
        boff[i] = (size_t)(n0 + rrow) * KTOT + seg * 8;
        bdst[i] = rrow * SROWB + seg * 16;
    }

#define FILL(k0v, bs) do { \
    const int _k = (k0v); uint32_t _sb = sb0 + (uint32_t)(bs) * STAGE; \
    _Pragma("unroll") for (int i = 0; i < 2; i++) cp_async16(_sb + adst[i],              Ah + aoff[i] + _k); \
    _Pragma("unroll") for (int i = 0; i < 2; i++) cp_async16(_sb + A_TILE_B + adst[i],   Al + aoff[i] + _k); \
    _Pragma("unroll") for (int i = 0; i < 4; i++) cp_async16(_sb + 2*A_TILE_B + bdst[i],            Bh + boff[i] + _k); \
    _Pragma("unroll") for (int i = 0; i < 4; i++) cp_async16(_sb + 2*A_TILE_B + B_TILE_B + bdst[i], Bl + boff[i] + _k); \
    cp_commit(); } while (0)

    FILL(0, 0); FILL(32, 1);

    float acc[4][8][4];
    #pragma unroll
    for (int i = 0; i < 4; i++)
        #pragma unroll
        for (int j = 0; j < 8; j++)
            #pragma unroll
            for (int c = 0; c < 4; c++) acc[i][j][c] = 0.0f;

    // ldmatrix per-lane byte offsets within a tile
    uint32_t a_rel = (uint32_t)(wm*64 + (lane & 15)) * SROWB + (lane >> 4) * 16;
    uint32_t b_rel = (uint32_t)(wn*64 + (lane & 7) + ((lane >> 4) & 1) * 8) * SROWB
                   + ((lane >> 3) & 1) * 16;

    int sbuf = 0;
    for (int s = 0; s < S; s++) {
        if (s < S - 1) cp_wait<1>(); else cp_wait<0>();
        __syncthreads();
        if (s + 2 < S) {
            int nb = sbuf + 2; if (nb >= NSTAGE) nb -= NSTAGE;
            FILL((s + 2) * 32, nb);
        }

        uint32_t base = sb0 + (uint32_t)sbuf * STAGE;
        #pragma unroll
        for (int ks = 0; ks < 2; ks++) {
            uint32_t ko = ks * 32;
            uint32_t ah[4][4], al[4][4], bh[8][2], bl[8][2];
            #pragma unroll
            for (int i = 0; i < 4; i++) {
                LDM4(ah[i][0], ah[i][1], ah[i][2], ah[i][3],
                     base + a_rel + i * (16*SROWB) + ko);
            }
            #pragma unroll
            for (int jj = 0; jj < 4; jj++) {
                uint32_t t0, t1, t2, t3;
                LDM4(t0, t1, t2, t3, base + 2*A_TILE_B + b_rel + jj * (16*SROWB) + ko);
                bh[jj*2][0] = t0; bh[jj*2][1] = t1; bh[jj*2+1][0] = t2; bh[jj*2+1][1] = t3;
            }
            #pragma unroll
            for (int i = 0; i < 4; i++)
                #pragma unroll
                for (int j = 0; j < 8; j++) MMA_BF16(acc[i][j], ah[i], bh[j]);

            #pragma unroll
            for (int jj = 0; jj < 4; jj++) {
                uint32_t t0, t1, t2, t3;
                LDM4(t0, t1, t2, t3, base + 2*A_TILE_B + B_TILE_B + b_rel + jj * (16*SROWB) + ko);
                bl[jj*2][0] = t0; bl[jj*2][1] = t1; bl[jj*2+1][0] = t2; bl[jj*2+1][1] = t3;
            }
            #pragma unroll
            for (int i = 0; i < 4; i++)
                #pragma unroll
                for (int j = 0; j < 8; j++) MMA_BF16(acc[i][j], ah[i], bl[j]);

            #pragma unroll
            for (int i = 0; i < 4; i++) {
                LDM4(al[i][0], al[i][1], al[i][2], al[i][3],
                     base + A_TILE_B + a_rel + i * (16*SROWB) + ko);
            }
            #pragma unroll
            for (int i = 0; i < 4; i++)
                #pragma unroll
                for (int j = 0; j < 8; j++) MMA_BF16(acc[i][j], al[i], bh[j]);
        }
        if (++sbuf == NSTAGE) sbuf = 0;
    }

    // ---- epilogue ----
    // acc[i][j]: c0,c1 -> row = base_r + lane/4,     cols col, col+1
    //            c2,c3 -> row = base_r + lane/4 + 8, cols col, col+1
    #pragma unroll
    for (int i = 0; i < 4; i++) {
        #pragma unroll
        for (int h = 0; h < 2; h++) {
            int r = row0 + wm*64 + i*16 + (lane >> 2) + h*8;
            float gs = 0.0f, v0 = 0.0f, v1 = 0.0f;
            int s0 = -1, s1 = -1;
            if (MODE == 3) {
                gs = g_gate[r];
                s0 = g_slot[2*r];     v0 = g_topv[2*r];
                s1 = g_slot[2*r + 1]; v1 = g_topv[2*r + 1];
            }
            if ((MODE == 0 || MODE == 1) && r >= rows) continue;
            #pragma unroll
            for (int j = 0; j < 8; j++) {
                int col = n0 + wn*64 + j*8 + (lane & 3)*2;
                float x0 = acc[i][j][h*2], x1 = acc[i][j][h*2 + 1];
                if (MODE == 0 || MODE == 2) {
                    float y0 = gelu_exact(x0), y1 = gelu_exact(x1);
                    __nv_bfloat16 h0 = __float2bfloat16(y0);
                    __nv_bfloat16 h1 = __float2bfloat16(y1);
                    __nv_bfloat162 hv(h0, h1);
                    __nv_bfloat162 lv(__float2bfloat16(y0 - __bfloat162float(h0)),
                                      __float2bfloat16(y1 - __bfloat162float(h1)));
                    size_t o;
                    if (MODE == 0) {
                        o = (size_t)(e*CAP + r) * DEXP + col;
                        *(__nv_bfloat162*)(g_Hhi + o) = hv;
                        *(__nv_bfloat162*)(g_Hlo + o) = lv;
                    } else {
                        o = (size_t)r * DFFN + col;
                        *(__nv_bfloat162*)(g_HShi + o) = hv;
                        *(__nv_bfloat162*)(g_HSlo + o) = lv;
                    }
                } else if (MODE == 1) {
                    size_t o = (size_t)(e*CAP + r) * DMODEL + col;
                    *(float2*)(g_EO + o) = make_float2(x0, x1);
                } else {
                    float o0 = gs * x0, o1 = gs * x1;
                    if (s0 >= 0) {
                        float2 ev = *(const float2*)(g_EO + (size_t)s0 * DMODEL + col);
                        o0 += v0 * ev.x; o1 += v0 * ev.y;
                    }
                    if (s1 >= 0) {
                        float2 ev = *(const float2*)(g_EO + (size_t)s1 * DMODEL + col);
                        o0 += v1 * ev.x; o1 += v1 * ev.y;
                    }
                    *(float2*)(outp + (size_t)r * DMODEL + col) = make_float2(o0, o1);
                }
            }
        }
    }
#undef FILL
}

// ---------------- stats ----------------
__global__ void stats_kernel(float* __restrict__ out, int out_size) {
    int e = threadIdx.x;
    if (e < NE && out_size >= NTOK*DMODEL + 2*NE) {
        out[NTOK*DMODEL + e]      = g_imp[e] / (float)NTOK;
        out[NTOK*DMODEL + NE + e] = (float)g_cnt[e] / ((float)NROUTE + 1e-12f);
    }
}

// ---------------- launch ----------------
extern "C" void kernel_launch(void* const* d_in, const int* in_sizes, int n_in,
                              void* d_out, int out_size) {
    const float* x   = (const float*)d_in[0];
    const float* rw  = (const float*)d_in[1];
    const float* gw  = (const float*)d_in[2];
    const float* w1  = (const float*)d_in[3];
    const float* w2  = (const float*)d_in[4];
    const float* sw1 = (const float*)d_in[5];
    const float* sw2 = (const float*)d_in[6];
    float* out = (float*)d_out;

    cudaFuncSetAttribute(gemm_mma<0>, cudaFuncAttributeMaxDynamicSharedMemorySize, GEMM_SMEM);
    cudaFuncSetAttribute(gemm_mma<1>, cudaFuncAttributeMaxDynamicSharedMemorySize, GEMM_SMEM);
    cudaFuncSetAttribute(gemm_mma<2>, cudaFuncAttributeMaxDynamicSharedMemorySize, GEMM_SMEM);
    cudaFuncSetAttribute(gemm_mma<3>, cudaFuncAttributeMaxDynamicSharedMemorySize, GEMM_SMEM);

    init_kernel<<<1, 32>>>();
    router_kernel<<<NTOK*32/256, 256>>>(x, rw, gw);
    scan_kernel<<<1, 256>>>();

    __nv_bfloat16 *xhi, *xlo, *w1hi, *w1lo, *w2hi, *w2lo, *s1hi, *s1lo, *s2hi, *s2lo;
    cudaGetSymbolAddress((void**)&xhi,  g_Xhi);  cudaGetSymbolAddress((void**)&xlo,  g_Xlo);
    cudaGetSymbolAddress((void**)&w1hi, g_W1hi); cudaGetSymbolAddress((void**)&w1lo, g_W1lo);
    cudaGetSymbolAddress((void**)&w2hi, g_W2hi); cudaGetSymbolAddress((void**)&w2lo, g_W2lo);
    cudaGetSymbolAddress((void**)&s1hi, g_SW1hi); cudaGetSymbolAddress((void**)&s1lo, g_SW1lo);
    cudaGetSymbolAddress((void**)&s2hi, g_SW2hi); cudaGetSymbolAddress((void**)&s2lo, g_SW2lo);

    k_split<<<(NTOK*DMODEL/4 + 255)/256, 256>>>(x,   xhi, xlo, NTOK*DMODEL/4);
    k_split<<<(DFFN*DMODEL/4 + 255)/256, 256>>>(sw1, s1hi, s1lo, DFFN*DMODEL/4);
    k_split<<<(DMODEL*DFFN/4 + 255)/256, 256>>>(sw2, s2hi, s2lo, DMODEL*DFFN/4);
    { dim3 g(DEXP/32, DMODEL/32, NE);  k_tsplit<<<g, dim3(32,8)>>>(w1, w1hi, w1lo, DMODEL, DEXP); }
    { dim3 g(DMODEL/32, DEXP/32, NE);  k_tsplit<<<g, dim3(32,8)>>>(w2, w2hi, w2lo, DEXP, DMODEL); }

    { dim3 g(DEXP/256,   CAP/128, NE); gemm_mma<0><<<g, 256, GEMM_SMEM>>>(out); }
    { dim3 g(DMODEL/256, CAP/128, NE); gemm_mma<1><<<g, 256, GEMM_SMEM>>>(out); }
    { dim3 g(DFFN/256,   NTOK/128, 1); gemm_mma<2><<<g, 256, GEMM_SMEM>>>(out); }
    { dim3 g(DMODEL/256, NTOK/128, 1); gemm_mma<3><<<g, 256, GEMM_SMEM>>>(out); }

    stats_kernel<<<1, 32>>>(out, out_size);
}

// round 8
// speedup vs baseline: 1.0557x; 1.0557x over previous
#include <cuda_runtime.h>
#include <cuda_bf16.h>
#include <math.h>
#include <stdint.h>

#define NTOK   8192
#define DMODEL 2048
#define DEXP   1024
#define DFFN   1024
#define NE     8
#define TOPK   2
#define CAP    2560
#define NROUTE (NTOK*TOPK)
#define NSLOT  (NE*CAP)

// ---------------- scratch (device globals) ----------------
__device__ float g_topv[NROUTE];
__device__ int   g_topi[NROUTE];
__device__ float g_gate[NTOK];
__device__ float g_imp[NE];
__device__ int   g_cnt[NE];
__device__ int   g_slot[NROUTE];
__device__ int   g_rows[NE];
__device__ int   g_rtok[NSLOT];

// bf16 split operands
__device__ __nv_bfloat16 g_Xhi[NTOK*DMODEL],  g_Xlo[NTOK*DMODEL];
__device__ __nv_bfloat16 g_W1hi[NE*DEXP*DMODEL], g_W1lo[NE*DEXP*DMODEL];   // [e][N=DEXP][K=DMODEL]
__device__ __nv_bfloat16 g_W2hi[NE*DMODEL*DEXP], g_W2lo[NE*DMODEL*DEXP];   // [e][N=DMODEL][K=DEXP]
__device__ __nv_bfloat16 g_SW1hi[DFFN*DMODEL], g_SW1lo[DFFN*DMODEL];       // [N=DFFN][K=DMODEL]
__device__ __nv_bfloat16 g_SW2hi[DMODEL*DFFN], g_SW2lo[DMODEL*DFFN];       // [N=DMODEL][K=DFFN]
__device__ __nv_bfloat16 g_Hhi[NSLOT*DEXP],   g_Hlo[NSLOT*DEXP];
__device__ __nv_bfloat16 g_HShi[NTOK*DFFN],   g_HSlo[NTOK*DFFN];
__device__ float g_EO[(size_t)NSLOT*DMODEL];

__device__ __forceinline__ float gelu_exact(float v) {
    return 0.5f * v * (1.0f + erff(v * 0.70710678118654752f));
}

// ---------------- PTX helpers (base ISA only: cp.async / ldmatrix / mma.sync) ----
__device__ __forceinline__ uint32_t smem_u32(const void* p) {
    uint32_t a;
    asm("{ .reg .u64 t; cvta.to.shared.u64 t, %1; cvt.u32.u64 %0, t; }" : "=r"(a) : "l"(p));
    return a;
}
__device__ __forceinline__ void cp_async16(uint32_t dst, const void* src) {
    asm volatile("cp.async.cg.shared.global [%0], [%1], 16;\n" :: "r"(dst), "l"(src));
}
__device__ __forceinline__ void cp_commit() { asm volatile("cp.async.commit_group;\n"); }
template<int N> __device__ __forceinline__ void cp_wait() {
    asm volatile("cp.async.wait_group %0;\n" :: "n"(N));
}

#define LDM4(r0, r1, r2, r3, addr) \
    asm volatile("ldmatrix.sync.aligned.m8n8.x4.shared.b16 {%0,%1,%2,%3}, [%4];" \
        : "=r"(r0), "=r"(r1), "=r"(r2), "=r"(r3) : "r"(addr))

#define MMA_BF16(d, a, b) \
    asm volatile("mma.sync.aligned.m16n8k16.row.col.f32.bf16.bf16.f32 " \
        "{%0,%1,%2,%3}, {%4,%5,%6,%7}, {%8,%9}, {%0,%1,%2,%3};" \
        : "+f"((d)[0]), "+f"((d)[1]), "+f"((d)[2]), "+f"((d)[3]) \
        : "r"((a)[0]), "r"((a)[1]), "r"((a)[2]), "r"((a)[3]), \
          "r"((b)[0]), "r"((b)[1]))

// ---------------- init ----------------
__global__ void init_kernel() {
    if (threadIdx.x < NE) { g_imp[threadIdx.x] = 0.0f; g_cnt[threadIdx.x] = 0; }
}

// ---------------- router: one warp per token ----------------
__global__ __launch_bounds__(256) void router_kernel(
    const float* __restrict__ x, const float* __restrict__ rw,
    const float* __restrict__ gw)
{
    __shared__ float s_imp[NE];
    __shared__ int   s_cnt[NE];
    if (threadIdx.x < NE) { s_imp[threadIdx.x] = 0.0f; s_cnt[threadIdx.x] = 0; }
    __syncthreads();

    int warp = (blockIdx.x * blockDim.x + threadIdx.x) >> 5;
    int lane = threadIdx.x & 31;
    if (warp < NTOK) {
        const float4* xv = (const float4*)(x + (size_t)warp * DMODEL);
        float acc[9];
        #pragma unroll
        for (int v = 0; v < 9; v++) acc[v] = 0.0f;
        for (int i = lane; i < DMODEL/4; i += 32) {
            float4 xa = xv[i];
            #pragma unroll
            for (int e = 0; e < NE; e++) {
                float4 w = ((const float4*)(rw + (size_t)e * DMODEL))[i];
                acc[e] += xa.x*w.x + xa.y*w.y + xa.z*w.z + xa.w*w.w;
            }
            float4 g = ((const float4*)gw)[i];
            acc[8] += xa.x*g.x + xa.y*g.y + xa.z*g.z + xa.w*g.w;
        }
        #pragma unroll
        for (int off = 16; off; off >>= 1) {
            #pragma unroll
            for (int v = 0; v < 9; v++)
                acc[v] += __shfl_xor_sync(0xffffffffu, acc[v], off);
        }
        if (lane == 0) {
            float mx = acc[0];
            #pragma unroll
            for (int e = 1; e < NE; e++) mx = fmaxf(mx, acc[e]);
            float p[NE]; float sum = 0.0f;
            #pragma unroll
            for (int e = 0; e < NE; e++) { p[e] = expf(acc[e] - mx); sum += p[e]; }
            float inv = 1.0f / sum;
            #pragma unroll
            for (int e = 0; e < NE; e++) p[e] *= inv;

            int i0 = 0; float v0 = p[0];
            #pragma unroll
            for (int e = 1; e < NE; e++) if (p[e] > v0) { v0 = p[e]; i0 = e; }
            int i1 = -1; float v1 = -1.0f;
            #pragma unroll
            for (int e = 0; e < NE; e++) if (e != i0 && p[e] > v1) { v1 = p[e]; i1 = e; }

            g_topi[warp*2]   = i0; g_topv[warp*2]   = v0;
            g_topi[warp*2+1] = i1; g_topv[warp*2+1] = v1;
            g_gate[warp] = 1.0f / (1.0f + expf(-acc[8]));
            #pragma unroll
            for (int e = 0; e < NE; e++) atomicAdd(&s_imp[e], p[e]);
            atomicAdd(&s_cnt[i0], 1);
            atomicAdd(&s_cnt[i1], 1);
        }
    }
    __syncthreads();
    if (threadIdx.x < NE) {
        atomicAdd(&g_imp[threadIdx.x], s_imp[threadIdx.x]);
        atomicAdd(&g_cnt[threadIdx.x], s_cnt[threadIdx.x]);
    }
}

// ---------------- stable routing scan (single block) ----------------
#define NCHUNK 64
#define CHUNK  (NROUTE/NCHUNK)   // 256
__global__ __launch_bounds__(256) void scan_kernel() {
    __shared__ unsigned char ids[NROUTE];
    __shared__ int hist[NCHUNK][NE];
    __shared__ int base[NCHUNK][NE];
    int tid = threadIdx.x;
    for (int r = tid; r < NROUTE; r += 256) ids[r] = (unsigned char)g_topi[r];
    __syncthreads();
    if (tid < NCHUNK) {
        int h[NE];
        #pragma unroll
        for (int e = 0; e < NE; e++) h[e] = 0;
        for (int j = 0; j < CHUNK; j++) h[ids[tid*CHUNK + j]]++;
        #pragma unroll
        for (int e = 0; e < NE; e++) hist[tid][e] = h[e];
    }
    __syncthreads();
    if (tid == 0) {
        int run[NE];
        #pragma unroll
        for (int e = 0; e < NE; e++) run[e] = 0;
        for (int c = 0; c < NCHUNK; c++) {
            #pragma unroll
            for (int e = 0; e < NE; e++) { base[c][e] = run[e]; run[e] += hist[c][e]; }
        }
        #pragma unroll
        for (int e = 0; e < NE; e++) g_rows[e] = (run[e] < CAP) ? run[e] : CAP;
    }
    __syncthreads();
    if (tid < NCHUNK) {
        int pos[NE];
        #pragma unroll
        for (int e = 0; e < NE; e++) pos[e] = base[tid][e];
        for (int j = 0; j < CHUNK; j++) {
            int r = tid*CHUNK + j;
            int e = ids[r];
            int rank = pos[e]++;
            if (rank < CAP) {
                int s = e*CAP + rank;
                g_slot[r]  = s;
                g_rtok[s]  = r >> 1;
            } else {
                g_slot[r] = -1;
            }
        }
    }
}

// ---------------- split conversion: 8 elems/thread, 16B hi/lo stores ----------------
__global__ __launch_bounds__(256) void k_split(
    const float* __restrict__ in, __nv_bfloat16* __restrict__ hi,
    __nv_bfloat16* __restrict__ lo, int n8)
{
    int i = blockIdx.x * 256 + threadIdx.x;
    if (i >= n8) return;
    float4 a = ((const float4*)in)[2*i];
    float4 b = ((const float4*)in)[2*i + 1];
    float v[8] = {a.x, a.y, a.z, a.w, b.x, b.y, b.z, b.w};
    uint32_t hw[4], lw[4];
    #pragma unroll
    for (int j = 0; j < 4; j++) {
        __nv_bfloat16 h0 = __float2bfloat16(v[2*j]);
        __nv_bfloat16 h1 = __float2bfloat16(v[2*j+1]);
        __nv_bfloat162 hp(h0, h1);
        __nv_bfloat162 lp(__float2bfloat16(v[2*j]   - __bfloat162float(h0)),
                          __float2bfloat16(v[2*j+1] - __bfloat162float(h1)));
        hw[j] = *(uint32_t*)&hp;
        lw[j] = *(uint32_t*)&lp;
    }
    ((uint4*)hi)[i] = make_uint4(hw[0], hw[1], hw[2], hw[3]);
    ((uint4*)lo)[i] = make_uint4(lw[0], lw[1], lw[2], lw[3]);
}

// ---------------- transpose + split: in [z][R][C] fp32 -> out [z][C][R] bf16 hi/lo --------
__global__ __launch_bounds__(256) void k_tsplit(
    const float* __restrict__ in, __nv_bfloat16* __restrict__ hi,
    __nv_bfloat16* __restrict__ lo, int R, int C)
{
    __shared__ float t[32][33];
    size_t mat = (size_t)blockIdx.z * R * C;
    int c0 = blockIdx.x * 32, r0 = blockIdx.y * 32;
    for (int y = threadIdx.y; y < 32; y += 8)
        t[y][threadIdx.x] = in[mat + (size_t)(r0 + y) * C + c0 + threadIdx.x];
    __syncthreads();
    for (int y = threadIdx.y; y < 32; y += 8) {
        float v = t[threadIdx.x][y];   // element (r0+tx, c0+y)
        __nv_bfloat16 h = __float2bfloat16(v);
        size_t o = mat + (size_t)(c0 + y) * R + r0 + threadIdx.x;
        hi[o] = h;
        lo[o] = __float2bfloat16(v - __bfloat162float(h));
    }
}

// ---------------- HMMA GEMM: CTA 256x128, Kstage 32, 3-stage cp.async, bf16x3 ----
// 512 threads = 16 warps in 4(M) x 4(N) grid, warp tile 64x32. (R6 winner config)
// MODE 0: routed gemm1  A=gather(Xhi/lo)  B=W1t[e]   K=2048 N=1024 -> gelu -> Hhi/lo
// MODE 1: routed gemm2  A=Hhi/lo[e]       B=W2t[e]   K=1024 N=2048 -> EO (fp32)
// MODE 2: shared gemm1  A=Xhi/lo          B=SW1      K=2048 N=1024 -> gelu -> HShi/lo
// MODE 3: shared gemm2  A=HShi/lo         B=SW2      K=1024 N=2048 -> combine -> out
//
// smem rows: 32 bf16 + 8 pad = 80B, conflict-free ldmatrix.
#define SROWB    80
#define A_TILE_B 20480         // 256*80
#define B_TILE_B 10240         // 128*80
#define STAGE    61440         // Ah + Al + Bh + Bl
#define NSTAGE   3
#define GEMM_SMEM (STAGE*NSTAGE)   // 184320

template<int MODE>
__global__ __launch_bounds__(512)
void gemm_mma(float* __restrict__ outp)
{
    constexpr int KTOT = (MODE == 0 || MODE == 2) ? DMODEL : DEXP;
    constexpr int S = KTOT / 32;

    extern __shared__ char smem[];
    uint32_t sb0 = smem_u32(smem);
    int tid = threadIdx.x, wid = tid >> 5, lane = tid & 31;
    int wm = wid >> 2, wn = wid & 3;     // warp grid 4 (M) x 4 (N)

    int e    = (MODE < 2) ? blockIdx.z : 0;
    int rows = (MODE < 2) ? g_rows[e] : NTOK;
    int row0 = blockIdx.y * 256;
    if (row0 >= rows) return;
    int n0 = blockIdx.x * 128;

    const __nv_bfloat16 *Ah, *Al, *Bh, *Bl;
    if (MODE == 0) { Ah = g_Xhi;  Al = g_Xlo;
                     Bh = g_W1hi + (size_t)e * DEXP * DMODEL;
                     Bl = g_W1lo + (size_t)e * DEXP * DMODEL; }
    if (MODE == 1) { Ah = g_Hhi;  Al = g_Hlo;
                     Bh = g_W2hi + (size_t)e * DMODEL * DEXP;
                     Bl = g_W2lo + (size_t)e * DMODEL * DEXP; }
    if (MODE == 2) { Ah = g_Xhi;  Al = g_Xlo;  Bh = g_SW1hi; Bl = g_SW1lo; }
    if (MODE == 3) { Ah = g_HShi; Al = g_HSlo; Bh = g_SW2hi; Bl = g_SW2lo; }

    // ---- fill addressing ----
    size_t aoff[2]; uint32_t adst[2];
    #pragma unroll
    for (int i = 0; i < 2; i++) {
        int c = tid + 512 * i;
        int rrow = c >> 2, seg = c & 3;
        size_t srow;
        if (MODE == 0) {
            int gr = row0 + rrow;
            int tok = (gr < rows) ? g_rtok[e * CAP + gr] : 0;
            srow = (size_t)tok * DMODEL;
        } else if (MODE == 1) {
            srow = (size_t)(e * CAP + row0 + rrow) * DEXP;
        } else {
            srow = (size_t)(row0 + rrow) * KTOT;
        }
        aoff[i] = srow + seg * 8;
        adst[i] = rrow * SROWB + seg * 16;
    }
    size_t boff; uint32_t bdst;
    {
        int rrow = tid >> 2, seg = tid & 3;
        boff = (size_t)(n0 + rrow) * KTOT + seg * 8;
        bdst = rrow * SROWB + seg * 16;
    }

#define FILL(k0v, bs) do { \
    const int _k = (k0v); uint32_t _sb = sb0 + (uint32_t)(bs) * STAGE; \
    _Pragma("unroll") for (int i = 0; i < 2; i++) cp_async16(_sb + adst[i],              Ah + aoff[i] + _k); \
    _Pragma("unroll") for (int i = 0; i < 2; i++) cp_async16(_sb + A_TILE_B + adst[i],   Al + aoff[i] + _k); \
    cp_async16(_sb + 2*A_TILE_B + bdst,              Bh + boff + _k); \
    cp_async16(_sb + 2*A_TILE_B + B_TILE_B + bdst,   Bl + boff + _k); \
    cp_commit(); } while (0)

    FILL(0, 0); FILL(32, 1);

    float acc[4][4][4];
    #pragma unroll
    for (int i = 0; i < 4; i++)
        #pragma unroll
        for (int j = 0; j < 4; j++)
            #pragma unroll
            for (int c = 0; c < 4; c++) acc[i][j][c] = 0.0f;

    // ldmatrix per-lane byte offsets within a tile
    uint32_t a_rel = (uint32_t)(wm*64 + (lane & 15)) * SROWB + (lane >> 4) * 16;
    uint32_t b_rel = (uint32_t)(wn*32 + (lane & 7) + ((lane >> 4) & 1) * 8) * SROWB
                   + ((lane >> 3) & 1) * 16;

    int sbuf = 0;
    for (int s = 0; s < S; s++) {
        if (s < S - 1) cp_wait<1>(); else cp_wait<0>();
        __syncthreads();
        if (s + 2 < S) {
            int nb = sbuf + 2; if (nb >= NSTAGE) nb -= NSTAGE;
            FILL((s + 2) * 32, nb);
        }

        uint32_t base = sb0 + (uint32_t)sbuf * STAGE;
        #pragma unroll
        for (int ks = 0; ks < 2; ks++) {
            uint32_t ko = ks * 32;
            uint32_t ah[4][4], al[4][4], bh[4][2], bl[4][2];
            #pragma unroll
            for (int i = 0; i < 4; i++) {
                LDM4(ah[i][0], ah[i][1], ah[i][2], ah[i][3],
                     base + a_rel + i * (16*SROWB) + ko);
            }
            #pragma unroll
            for (int jj = 0; jj < 2; jj++) {
                uint32_t t0, t1, t2, t3;
                LDM4(t0, t1, t2, t3, base + 2*A_TILE_B + b_rel + jj * (16*SROWB) + ko);
                bh[jj*2][0] = t0; bh[jj*2][1] = t1; bh[jj*2+1][0] = t2; bh[jj*2+1][1] = t3;
            }
            #pragma unroll
            for (int i = 0; i < 4; i++)
                #pragma unroll
                for (int j = 0; j < 4; j++) MMA_BF16(acc[i][j], ah[i], bh[j]);

            #pragma unroll
            for (int jj = 0; jj < 2; jj++) {
                uint32_t t0, t1, t2, t3;
                LDM4(t0, t1, t2, t3, base + 2*A_TILE_B + B_TILE_B + b_rel + jj * (16*SROWB) + ko);
                bl[jj*2][0] = t0; bl[jj*2][1] = t1; bl[jj*2+1][0] = t2; bl[jj*2+1][1] = t3;
            }
            #pragma unroll
            for (int i = 0; i < 4; i++)
                #pragma unroll
                for (int j = 0; j < 4; j++) MMA_BF16(acc[i][j], ah[i], bl[j]);

            #pragma unroll
            for (int i = 0; i < 4; i++) {
                LDM4(al[i][0], al[i][1], al[i][2], al[i][3],
                     base + A_TILE_B + a_rel + i * (16*SROWB) + ko);
            }
            #pragma unroll
            for (int i = 0; i < 4; i++)
                #pragma unroll
                for (int j = 0; j < 4; j++) MMA_BF16(acc[i][j], al[i], bh[j]);
        }
        if (++sbuf == NSTAGE) sbuf = 0;
    }

    // ---- epilogue ----
    #pragma unroll
    for (int i = 0; i < 4; i++) {
        #pragma unroll
        for (int h = 0; h < 2; h++) {
            int r = row0 + wm*64 + i*16 + (lane >> 2) + h*8;
            float gs = 0.0f, v0 = 0.0f, v1 = 0.0f;
            int s0 = -1, s1 = -1;
            if (MODE == 3) {
                gs = g_gate[r];
                s0 = g_slot[2*r];     v0 = g_topv[2*r];
                s1 = g_slot[2*r + 1]; v1 = g_topv[2*r + 1];
            }
            if ((MODE == 0 || MODE == 1) && r >= rows) continue;
            #pragma unroll
            for (int j = 0; j < 4; j++) {
                int col = n0 + wn*32 + j*8 + (lane & 3)*2;
                float x0 = acc[i][j][h*2], x1 = acc[i][j][h*2 + 1];
                if (MODE == 0 || MODE == 2) {
                    float y0 = gelu_exact(x0), y1 = gelu_exact(x1);
                    __nv_bfloat16 h0 = __float2bfloat16(y0);
                    __nv_bfloat16 h1 = __float2bfloat16(y1);
                    __nv_bfloat162 hv(h0, h1);
                    __nv_bfloat162 lv(__float2bfloat16(y0 - __bfloat162float(h0)),
                                      __float2bfloat16(y1 - __bfloat162float(h1)));
                    size_t o;
                    if (MODE == 0) {
                        o = (size_t)(e*CAP + r) * DEXP + col;
                        *(__nv_bfloat162*)(g_Hhi + o) = hv;
                        *(__nv_bfloat162*)(g_Hlo + o) = lv;
                    } else {
                        o = (size_t)r * DFFN + col;
                        *(__nv_bfloat162*)(g_HShi + o) = hv;
                        *(__nv_bfloat162*)(g_HSlo + o) = lv;
                    }
                } else if (MODE == 1) {
                    size_t o = (size_t)(e*CAP + r) * DMODEL + col;
                    *(float2*)(g_EO + o) = make_float2(x0, x1);
                } else {
                    float o0 = gs * x0, o1 = gs * x1;
                    if (s0 >= 0) {
                        float2 ev = *(const float2*)(g_EO + (size_t)s0 * DMODEL + col);
                        o0 += v0 * ev.x; o1 += v0 * ev.y;
                    }
                    if (s1 >= 0) {
                        float2 ev = *(const float2*)(g_EO + (size_t)s1 * DMODEL + col);
                        o0 += v1 * ev.x; o1 += v1 * ev.y;
                    }
                    *(float2*)(outp + (size_t)r * DMODEL + col) = make_float2(o0, o1);
                }
            }
        }
    }
#undef FILL
}

// ---------------- stats ----------------
__global__ void stats_kernel(float* __restrict__ out, int out_size) {
    int e = threadIdx.x;
    if (e < NE && out_size >= NTOK*DMODEL + 2*NE) {
        out[NTOK*DMODEL + e]      = g_imp[e] / (float)NTOK;
        out[NTOK*DMODEL + NE + e] = (float)g_cnt[e] / ((float)NROUTE + 1e-12f);
    }
}

// ---------------- launch ----------------
// Launch order is chosen so ncu (-s 5 -c 1) profiles gemm_mma<2>:
//   0-2: k_split x3   3-4: k_tsplit x2   5: gemm_mma<2>   6: init  7: router
//   8: scan   9: gemm_mma<0>   10: gemm_mma<1>   11: gemm_mma<3>   12: stats
extern "C" void kernel_launch(void* const* d_in, const int* in_sizes, int n_in,
                              void* d_out, int out_size) {
    const float* x   = (const float*)d_in[0];
    const float* rw  = (const float*)d_in[1];
    const float* gw  = (const float*)d_in[2];
    const float* w1  = (const float*)d_in[3];
    const float* w2  = (const float*)d_in[4];
    const float* sw1 = (const float*)d_in[5];
    const float* sw2 = (const float*)d_in[6];
    float* out = (float*)d_out;

    cudaFuncSetAttribute(gemm_mma<0>, cudaFuncAttributeMaxDynamicSharedMemorySize, GEMM_SMEM);
    cudaFuncSetAttribute(gemm_mma<1>, cudaFuncAttributeMaxDynamicSharedMemorySize, GEMM_SMEM);
    cudaFuncSetAttribute(gemm_mma<2>, cudaFuncAttributeMaxDynamicSharedMemorySize, GEMM_SMEM);
    cudaFuncSetAttribute(gemm_mma<3>, cudaFuncAttributeMaxDynamicSharedMemorySize, GEMM_SMEM);

    __nv_bfloat16 *xhi, *xlo, *w1hi, *w1lo, *w2hi, *w2lo, *s1hi, *s1lo, *s2hi, *s2lo;
    cudaGetSymbolAddress((void**)&xhi,  g_Xhi);  cudaGetSymbolAddress((void**)&xlo,  g_Xlo);
    cudaGetSymbolAddress((void**)&w1hi, g_W1hi); cudaGetSymbolAddress((void**)&w1lo, g_W1lo);
    cudaGetSymbolAddress((void**)&w2hi, g_W2hi); cudaGetSymbolAddress((void**)&w2lo, g_W2lo);
    cudaGetSymbolAddress((void**)&s1hi, g_SW1hi); cudaGetSymbolAddress((void**)&s1lo, g_SW1lo);
    cudaGetSymbolAddress((void**)&s2hi, g_SW2hi); cudaGetSymbolAddress((void**)&s2lo, g_SW2lo);

    // conversions first (depend only on inputs)
    k_split<<<(NTOK*DMODEL/8 + 255)/256, 256>>>(x,   xhi, xlo, NTOK*DMODEL/8);
    k_split<<<(DFFN*DMODEL/8 + 255)/256, 256>>>(sw1, s1hi, s1lo, DFFN*DMODEL/8);
    k_split<<<(DMODEL*DFFN/8 + 255)/256, 256>>>(sw2, s2hi, s2lo, DMODEL*DFFN/8);
    { dim3 g(DEXP/32, DMODEL/32, NE);  k_tsplit<<<g, dim3(32,8)>>>(w1, w1hi, w1lo, DMODEL, DEXP); }
    { dim3 g(DMODEL/32, DEXP/32, NE);  k_tsplit<<<g, dim3(32,8)>>>(w2, w2hi, w2lo, DEXP, DMODEL); }

    // launch #5: shared gemm1 — the one ncu profiles
    { dim3 g(DFFN/128,   NTOK/256, 1); gemm_mma<2><<<g, 512, GEMM_SMEM>>>(out); }

    init_kernel<<<1, 32>>>();
    router_kernel<<<NTOK*32/256, 256>>>(x, rw, gw);
    scan_kernel<<<1, 256>>>();

    { dim3 g(DEXP/128,   CAP/256, NE); gemm_mma<0><<<g, 512, GEMM_SMEM>>>(out); }
    { dim3 g(DMODEL/128, CAP/256, NE); gemm_mma<1><<<g, 512, GEMM_SMEM>>>(out); }
    { dim3 g(DMODEL/128, NTOK/256, 1); gemm_mma<3><<<g, 512, GEMM_SMEM>>>(out); }

    stats_kernel<<<1, 32>>>(out, out_size);
}